// round 7
// baseline (speedup 1.0000x reference)
#include <cuda_runtime.h>
#include <cstdint>
#include <math.h>

#define NN 10000
#define NE 320000
#define NH 128
#define NPAD 10112            // 79 * 128
#define TS_STRIDE 129
#define QS 144                // int8 tile row stride (bytes): 144 mod 128 = 16 -> conflict-free

// ---------------- scratch ----------------------------------------------------
__device__ float g_hw[(size_t)NN * NH];
__device__ int8_t g_xq[(size_t)NPAD * NH];   // level-1 quant
__device__ int8_t g_xp[(size_t)NPAD * NH];   // level-2 quant of residual
__device__ float  g_s[NPAD];                 // per-row scale (level-2 scale = s/254)
__device__ int g_deg[NN];
__device__ int g_off[NN + 1];
__device__ int g_fill[NN];
__device__ int g_csr[NE];

// ============================================================================
// CSR build
__global__ void csr_zero_kernel() {
    int i = blockIdx.x * 256 + threadIdx.x;
    if (i < NN) { g_deg[i] = 0; g_fill[i] = 0; }
}
__global__ void csr_count_kernel(const int* __restrict__ ed) {
    int e = blockIdx.x * 256 + threadIdx.x;
    if (e < NE) atomicAdd(&g_deg[ed[e]], 1);
}
__global__ void csr_scan_kernel() {
    __shared__ int part[1024];
    int tid = threadIdx.x;
    int base = tid * 10;
    int s = 0;
    #pragma unroll
    for (int q = 0; q < 10; ++q) { int i = base + q; if (i < NN) s += g_deg[i]; }
    part[tid] = s;
    __syncthreads();
    #pragma unroll
    for (int off = 1; off < 1024; off <<= 1) {
        int v = (tid >= off) ? part[tid - off] : 0;
        __syncthreads();
        part[tid] += v;
        __syncthreads();
    }
    int run = (tid == 0) ? 0 : part[tid - 1];
    #pragma unroll
    for (int q = 0; q < 10; ++q) {
        int i = base + q;
        if (i < NN) { g_off[i] = run; run += g_deg[i]; }
    }
    if (tid == 0) g_off[NN] = part[1023];
}
__global__ void csr_fill_kernel(const int* __restrict__ es,
                                const int* __restrict__ ed) {
    int e = blockIdx.x * 256 + threadIdx.x;
    if (e < NE) {
        int d = ed[e];
        int pos = atomicAdd(&g_fill[d], 1);
        g_csr[g_off[d] + pos] = es[e];
    }
}

// ============================================================================
// hw = h @ W (fp32 SIMT, small)
__device__ __forceinline__ void load_tileT(const float* __restrict__ src,
                                           int row0, int maxrows,
                                           float* __restrict__ Ts) {
    int lane = threadIdx.x & 31, w = threadIdx.x >> 5;
    #pragma unroll
    for (int rr = 0; rr < 16; ++rr) {
        int r = w * 16 + rr;
        bool ok = (row0 + r < maxrows);
        const float* p = src + (size_t)(row0 + r) * NH;
        #pragma unroll
        for (int q = 0; q < 4; ++q) {
            int k = lane + 32 * q;
            Ts[k * TS_STRIDE + r] = ok ? p[k] : 0.0f;
        }
    }
}
__device__ __forceinline__ void load_tile_rowmajor(const float* __restrict__ src,
                                                   float* __restrict__ Ts) {
    int lane = threadIdx.x & 31, w = threadIdx.x >> 5;
    #pragma unroll
    for (int rr = 0; rr < 16; ++rr) {
        int k = w * 16 + rr;
        #pragma unroll
        for (int q = 0; q < 4; ++q) {
            int n = lane + 32 * q;
            Ts[k * TS_STRIDE + n] = src[k * NH + n];
        }
    }
}
extern "C" __global__ void gemm_hw_kernel(const float* __restrict__ h,
                                          const float* __restrict__ W) {
    extern __shared__ float smemf[];
    float* As = smemf;
    float* Bs = smemf + 128 * TS_STRIDE;
    int row0 = blockIdx.x * 128;
    load_tileT(h, row0, NN, As);
    load_tile_rowmajor(W, Bs);
    __syncthreads();
    int tx = threadIdx.x & 15, ty = threadIdx.x >> 4;
    float acc[8][8] = {};
    #pragma unroll 8
    for (int k = 0; k < 128; ++k) {
        float a[8], b[8];
        #pragma unroll
        for (int i = 0; i < 8; ++i) a[i] = As[k * TS_STRIDE + ty + 16 * i];
        #pragma unroll
        for (int j = 0; j < 8; ++j) b[j] = Bs[k * TS_STRIDE + tx + 16 * j];
        #pragma unroll
        for (int i = 0; i < 8; ++i)
            #pragma unroll
            for (int j = 0; j < 8; ++j)
                acc[i][j] = fmaf(a[i], b[j], acc[i][j]);
    }
    #pragma unroll
    for (int i = 0; i < 8; ++i) {
        int m = row0 + ty + 16 * i;
        if (m < NN)
            #pragma unroll
            for (int j = 0; j < 8; ++j)
                g_hw[(size_t)m * NH + tx + 16 * j] = acc[i][j];
    }
}

// ============================================================================
// fused gather + bias + relu + two-level int8 quantization (one block per row)
extern "C" __global__ void gather_fuse_kernel(const float* __restrict__ b) {
    __shared__ float red[128];
    int node = blockIdx.x;
    int c = threadIdx.x;
    size_t o = (size_t)node * NH + c;
    float v = 0.0f;
    if (node < NN) {
        int beg = g_off[node];
        int end = g_off[node + 1];
        float acc = 0.0f;
        int e = beg;
        for (; e + 4 <= end; e += 4) {
            int s0 = g_csr[e], s1 = g_csr[e + 1], s2 = g_csr[e + 2], s3 = g_csr[e + 3];
            float v0 = g_hw[(size_t)s0 * NH + c];
            float v1 = g_hw[(size_t)s1 * NH + c];
            float v2 = g_hw[(size_t)s2 * NH + c];
            float v3 = g_hw[(size_t)s3 * NH + c];
            acc += (v0 + v1) + (v2 + v3);
        }
        for (; e < end; ++e)
            acc += g_hw[(size_t)g_csr[e] * NH + c];
        v = acc + b[c];
        v = v > 0.0f ? v : 0.0f;
    }
    // block max (row max)
    red[c] = v;
    __syncthreads();
    #pragma unroll
    for (int off = 64; off > 0; off >>= 1) {
        if (c < off) red[c] = fmaxf(red[c], red[c + off]);
        __syncthreads();
    }
    float vmax = red[0];
    float s = (vmax > 0.0f) ? vmax * (1.0f / 127.0f) : 1.0f;
    float t = s * (1.0f / 254.0f);
    int q = (int)rintf(v / s);
    if (q > 127) q = 127;
    float r = v - s * (float)q;
    int p = (int)rintf(r / t);
    if (p > 127) p = 127; if (p < -127) p = -127;
    g_xq[o] = (int8_t)q;
    g_xp[o] = (int8_t)p;
    if (c == 0) g_s[node] = (node < NN && vmax > 0.0f) ? s : 0.0f;
}

// ============================================================================
// xxt: int8 m16n8k32, D = s_m s_n (QQ + (QP + PQ)/254), symmetric tiles
#define QT_BYTES (128 * QS)                  // 18432
#define OFF_AQ 0
#define OFF_AP QT_BYTES
#define OFF_BQ (2 * QT_BYTES)
#define OFF_BP (3 * QT_BYTES)
#define OFF_SA (4 * QT_BYTES)                // 128 floats
#define OFF_SB (4 * QT_BYTES + 512)
#define SMEM_XXT_BYTES (4 * QT_BYTES + 1024) // 74752

__device__ __forceinline__ void cp16(uint32_t dst, const void* src) {
    asm volatile("cp.async.cg.shared.global [%0], [%1], 16;" :: "r"(dst), "l"(src));
}
#define CP_COMMIT() asm volatile("cp.async.commit_group;" ::: "memory")
#define CP_WAIT()   asm volatile("cp.async.wait_all;" ::: "memory")
__device__ __forceinline__ uint32_t smem_u32_of(const void* p) {
    uint32_t a;
    asm("{ .reg .u64 t; cvta.to.shared.u64 t, %1; cvt.u32.u64 %0, t; }"
        : "=r"(a) : "l"(p));
    return a;
}
__device__ __forceinline__ void load_q_tile_async(const int8_t* __restrict__ src,
                                                  int row0, uint32_t dst) {
    int tid = threadIdx.x;  // 256 threads, 4 x 16B each (1024 chunks)
    #pragma unroll
    for (int it = 0; it < 4; ++it) {
        int chunk = it * 256 + tid;
        int row = chunk >> 3, c16 = chunk & 7;
        cp16(dst + row * QS + c16 * 16,
             src + (size_t)(row0 + row) * NH + c16 * 16);
    }
}
__device__ __forceinline__ void mma_s8(int d[4], uint32_t a0, uint32_t a1,
                                       uint32_t a2, uint32_t a3,
                                       uint32_t b0, uint32_t b1) {
    asm volatile(
        "mma.sync.aligned.m16n8k32.row.col.s32.s8.s8.s32 "
        "{%0,%1,%2,%3}, {%4,%5,%6,%7}, {%8,%9}, {%0,%1,%2,%3};"
        : "+r"(d[0]), "+r"(d[1]), "+r"(d[2]), "+r"(d[3])
        : "r"(a0), "r"(a1), "r"(a2), "r"(a3), "r"(b0), "r"(b1));
}

extern "C" __global__ void __launch_bounds__(256, 1)
xxt_mma_kernel(float* __restrict__ out) {
    // triangular block decode: t -> (bym, bxn), bym <= bxn, 79x79 upper tri
    int t = blockIdx.x;
    int r = (int)((159.0f - sqrtf(25281.0f - 8.0f * (float)t)) * 0.5f);
    if (r < 0) r = 0; if (r > 78) r = 78;
    while ((r + 1) * 79 - ((r + 1) * r) / 2 <= t) ++r;
    while (r * 79 - (r * (r - 1)) / 2 > t) --r;
    int bym = r;
    int bxn = r + (t - (r * 79 - (r * (r - 1)) / 2));
    bool diag = (bxn == bym);

    extern __shared__ char smem[];
    uint32_t sb = smem_u32_of(smem);
    int tid = threadIdx.x, lane = tid & 31, wid = tid >> 5;

    load_q_tile_async(g_xq, bym * 128, sb + OFF_AQ);
    load_q_tile_async(g_xp, bym * 128, sb + OFF_AP);
    if (!diag) {
        load_q_tile_async(g_xq, bxn * 128, sb + OFF_BQ);
        load_q_tile_async(g_xp, bxn * 128, sb + OFF_BP);
    }
    if (tid < 32) cp16(sb + OFF_SA + tid * 16, g_s + bym * 128 + tid * 4);
    else if (tid < 64 && !diag)
        cp16(sb + OFF_SB + (tid - 32) * 16, g_s + bxn * 128 + (tid - 32) * 4);
    CP_COMMIT(); CP_WAIT();
    __syncthreads();

    const char* Aq = smem + OFF_AQ;
    const char* Ap = smem + OFF_AP;
    const char* Bq = diag ? Aq : (smem + OFF_BQ);
    const char* Bp = diag ? Ap : (smem + OFF_BP);
    const float* sA = (const float*)(smem + OFF_SA);
    const float* sB = diag ? sA : (const float*)(smem + OFF_SB);

    int wm = wid & 1;        // 64-row half
    int wn = wid >> 1;       // 32-col quarter
    int frow = lane >> 2;
    int fcol = 2 * (lane & 3);

    // per-lane fragment base offsets (bytes)
    int aoff = (wm * 64 + frow) * QS + 4 * (lane & 3);
    int boff = (wn * 32 + frow) * QS + 4 * (lane & 3);

    int accQ[4][4][4] = {};    // Q*Q^T
    int accX[4][4][4] = {};    // Q*P^T + P*Q^T (shared coefficient /254)

    #pragma unroll
    for (int ks = 0; ks < 4; ++ks) {
        int kb = ks * 32;
        uint32_t bq[4][2], bp[4][2];
        #pragma unroll
        for (int j = 0; j < 4; ++j) {
            int o0 = boff + j * 8 * QS + kb;
            bq[j][0] = *(const uint32_t*)(Bq + o0);
            bq[j][1] = *(const uint32_t*)(Bq + o0 + 16);
            bp[j][0] = *(const uint32_t*)(Bp + o0);
            bp[j][1] = *(const uint32_t*)(Bp + o0 + 16);
        }
        #pragma unroll
        for (int i = 0; i < 4; ++i) {
            int o0 = aoff + i * 16 * QS + kb;
            uint32_t aq0 = *(const uint32_t*)(Aq + o0);
            uint32_t aq1 = *(const uint32_t*)(Aq + o0 + 8 * QS);
            uint32_t aq2 = *(const uint32_t*)(Aq + o0 + 16);
            uint32_t aq3 = *(const uint32_t*)(Aq + o0 + 8 * QS + 16);
            uint32_t ap0 = *(const uint32_t*)(Ap + o0);
            uint32_t ap1 = *(const uint32_t*)(Ap + o0 + 8 * QS);
            uint32_t ap2 = *(const uint32_t*)(Ap + o0 + 16);
            uint32_t ap3 = *(const uint32_t*)(Ap + o0 + 8 * QS + 16);
            #pragma unroll
            for (int j = 0; j < 4; ++j) {
                mma_s8(accQ[i][j], aq0, aq1, aq2, aq3, bq[j][0], bq[j][1]);
                mma_s8(accX[i][j], aq0, aq1, aq2, aq3, bp[j][0], bp[j][1]);
                mma_s8(accX[i][j], ap0, ap1, ap2, ap3, bq[j][0], bq[j][1]);
            }
        }
    }

    int m0 = bym * 128, n0 = bxn * 128;
    bool edge = (n0 + 127 >= NN) || (m0 + 127 >= NN);
    const float inv254 = 1.0f / 254.0f;

    #pragma unroll
    for (int i = 0; i < 4; ++i) {
        int rr = wm * 64 + i * 16 + frow;
        float sm1 = sA[rr], sm2 = sA[rr + 8];
        #pragma unroll
        for (int j = 0; j < 4; ++j) {
            int c = wn * 32 + j * 8 + fcol;
            float sn1 = sB[c], sn2 = sB[c + 1];
            float v0 = sm1 * sn1 * ((float)accQ[i][j][0] + (float)accX[i][j][0] * inv254);
            float v1 = sm1 * sn2 * ((float)accQ[i][j][1] + (float)accX[i][j][1] * inv254);
            float v2 = sm2 * sn1 * ((float)accQ[i][j][2] + (float)accX[i][j][2] * inv254);
            float v3 = sm2 * sn2 * ((float)accQ[i][j][3] + (float)accX[i][j][3] * inv254);

            // main store C[m][n]
            if (!edge) {
                *(float2*)&out[(size_t)(m0 + rr) * NN + n0 + c] = make_float2(v0, v1);
                *(float2*)&out[(size_t)(m0 + rr + 8) * NN + n0 + c] = make_float2(v2, v3);
            } else {
                int m1 = m0 + rr, m2 = m0 + rr + 8, n = n0 + c;
                if (m1 < NN) {
                    if (n < NN)     out[(size_t)m1 * NN + n]     = v0;
                    if (n + 1 < NN) out[(size_t)m1 * NN + n + 1] = v1;
                }
                if (m2 < NN) {
                    if (n < NN)     out[(size_t)m2 * NN + n]     = v2;
                    if (n + 1 < NN) out[(size_t)m2 * NN + n + 1] = v3;
                }
            }
            // mirror store C[n][m]
            if (!diag) {
                size_t m1 = (size_t)(m0 + rr), m2 = (size_t)(m0 + rr + 8);
                size_t n1 = (size_t)(n0 + c),  n2 = (size_t)(n0 + c + 1);
                if (n0 + 127 < NN) {
                    out[n1 * NN + m1] = v0;
                    out[n2 * NN + m1] = v1;
                    out[n1 * NN + m2] = v2;
                    out[n2 * NN + m2] = v3;
                } else {
                    if (n1 < NN) { out[n1 * NN + m1] = v0; out[n1 * NN + m2] = v2; }
                    if (n2 < NN) { out[n2 * NN + m1] = v1; out[n2 * NN + m2] = v3; }
                }
            }
        }
    }
}

// ============================================================================
extern "C" void kernel_launch(void* const* d_in, const int* in_sizes, int n_in,
                              void* d_out, int out_size) {
    const float* h  = (const float*)d_in[0];
    const float* W  = (const float*)d_in[1];
    const float* b  = (const float*)d_in[2];
    const int*   es = (const int*)d_in[3];
    const int*   ed = (const int*)d_in[4];
    float*       out = (float*)d_out;

    const size_t smem_hw = (size_t)2 * 128 * TS_STRIDE * sizeof(float);
    cudaFuncSetAttribute(gemm_hw_kernel,
                         cudaFuncAttributeMaxDynamicSharedMemorySize, (int)smem_hw);
    cudaFuncSetAttribute(xxt_mma_kernel,
                         cudaFuncAttributeMaxDynamicSharedMemorySize, SMEM_XXT_BYTES);

    csr_zero_kernel<<<(NN + 255) / 256, 256>>>();
    csr_count_kernel<<<(NE + 255) / 256, 256>>>(ed);
    csr_scan_kernel<<<1, 1024>>>();
    csr_fill_kernel<<<(NE + 255) / 256, 256>>>(es, ed);

    gemm_hw_kernel<<<(NN + 127) / 128, 256, smem_hw>>>(h, W);
    gather_fuse_kernel<<<NPAD, 128>>>(b);

    xxt_mma_kernel<<<3160, 256, SMEM_XXT_BYTES>>>(out);
}

// round 8
// speedup vs baseline: 2.6010x; 2.6010x over previous
#include <cuda_runtime.h>
#include <cuda_fp16.h>
#include <cstdint>
#include <math.h>

#define NN 10000
#define NE 320000
#define NH 128
#define NPAD 10112            // 79 * 128
#define TS_STRIDE 129
#define XT_STRIDE 136         // f16 tile stride: 272B/row == 16 mod 128 -> conflict-free
#define RS (XT_STRIDE * 2)

// ---------------- scratch ----------------------------------------------------
__device__ float g_hw[(size_t)NN * NH];
__device__ __half g_y[(size_t)NPAD * NH];    // fp16(x), zero-padded
__device__ int g_deg[NN];
__device__ int g_off[NN + 1];
__device__ int g_fill[NN];
__device__ int g_csr[NE];

// ============================================================================
// CSR build
__global__ void csr_zero_kernel() {
    int i = blockIdx.x * 256 + threadIdx.x;
    if (i < NN) { g_deg[i] = 0; g_fill[i] = 0; }
}
__global__ void csr_count_kernel(const int* __restrict__ ed) {
    int e = blockIdx.x * 256 + threadIdx.x;
    if (e < NE) atomicAdd(&g_deg[ed[e]], 1);
}
__global__ void csr_scan_kernel() {
    __shared__ int part[1024];
    int tid = threadIdx.x;
    int base = tid * 10;
    int s = 0;
    #pragma unroll
    for (int q = 0; q < 10; ++q) { int i = base + q; if (i < NN) s += g_deg[i]; }
    part[tid] = s;
    __syncthreads();
    #pragma unroll
    for (int off = 1; off < 1024; off <<= 1) {
        int v = (tid >= off) ? part[tid - off] : 0;
        __syncthreads();
        part[tid] += v;
        __syncthreads();
    }
    int run = (tid == 0) ? 0 : part[tid - 1];
    #pragma unroll
    for (int q = 0; q < 10; ++q) {
        int i = base + q;
        if (i < NN) { g_off[i] = run; run += g_deg[i]; }
    }
    if (tid == 0) g_off[NN] = part[1023];
}
__global__ void csr_fill_kernel(const int* __restrict__ es,
                                const int* __restrict__ ed) {
    int e = blockIdx.x * 256 + threadIdx.x;
    if (e < NE) {
        int d = ed[e];
        int pos = atomicAdd(&g_fill[d], 1);
        g_csr[g_off[d] + pos] = es[e];
    }
}

// ============================================================================
// hw = h @ W (fp32 SIMT, small)
__device__ __forceinline__ void load_tileT(const float* __restrict__ src,
                                           int row0, int maxrows,
                                           float* __restrict__ Ts) {
    int lane = threadIdx.x & 31, w = threadIdx.x >> 5;
    #pragma unroll
    for (int rr = 0; rr < 16; ++rr) {
        int r = w * 16 + rr;
        bool ok = (row0 + r < maxrows);
        const float* p = src + (size_t)(row0 + r) * NH;
        #pragma unroll
        for (int q = 0; q < 4; ++q) {
            int k = lane + 32 * q;
            Ts[k * TS_STRIDE + r] = ok ? p[k] : 0.0f;
        }
    }
}
__device__ __forceinline__ void load_tile_rowmajor(const float* __restrict__ src,
                                                   float* __restrict__ Ts) {
    int lane = threadIdx.x & 31, w = threadIdx.x >> 5;
    #pragma unroll
    for (int rr = 0; rr < 16; ++rr) {
        int k = w * 16 + rr;
        #pragma unroll
        for (int q = 0; q < 4; ++q) {
            int n = lane + 32 * q;
            Ts[k * TS_STRIDE + n] = src[k * NH + n];
        }
    }
}
extern "C" __global__ void gemm_hw_kernel(const float* __restrict__ h,
                                          const float* __restrict__ W) {
    extern __shared__ float smemf[];
    float* As = smemf;
    float* Bs = smemf + 128 * TS_STRIDE;
    int row0 = blockIdx.x * 128;
    load_tileT(h, row0, NN, As);
    load_tile_rowmajor(W, Bs);
    __syncthreads();
    int tx = threadIdx.x & 15, ty = threadIdx.x >> 4;
    float acc[8][8] = {};
    #pragma unroll 8
    for (int k = 0; k < 128; ++k) {
        float a[8], b[8];
        #pragma unroll
        for (int i = 0; i < 8; ++i) a[i] = As[k * TS_STRIDE + ty + 16 * i];
        #pragma unroll
        for (int j = 0; j < 8; ++j) b[j] = Bs[k * TS_STRIDE + tx + 16 * j];
        #pragma unroll
        for (int i = 0; i < 8; ++i)
            #pragma unroll
            for (int j = 0; j < 8; ++j)
                acc[i][j] = fmaf(a[i], b[j], acc[i][j]);
    }
    #pragma unroll
    for (int i = 0; i < 8; ++i) {
        int m = row0 + ty + 16 * i;
        if (m < NN)
            #pragma unroll
            for (int j = 0; j < 8; ++j)
                g_hw[(size_t)m * NH + tx + 16 * j] = acc[i][j];
    }
}

// ============================================================================
// fused gather + bias + relu + fp16 quantize (one block per row)
extern "C" __global__ void gather_fuse_kernel(const float* __restrict__ b) {
    int node = blockIdx.x;
    int c = threadIdx.x;
    size_t o = (size_t)node * NH + c;
    if (node >= NN) { g_y[o] = __float2half(0.0f); return; }
    int beg = g_off[node];
    int end = g_off[node + 1];
    float acc = 0.0f;
    int e = beg;
    for (; e + 4 <= end; e += 4) {
        int s0 = g_csr[e], s1 = g_csr[e + 1], s2 = g_csr[e + 2], s3 = g_csr[e + 3];
        float v0 = g_hw[(size_t)s0 * NH + c];
        float v1 = g_hw[(size_t)s1 * NH + c];
        float v2 = g_hw[(size_t)s2 * NH + c];
        float v3 = g_hw[(size_t)s3 * NH + c];
        acc += (v0 + v1) + (v2 + v3);
    }
    for (; e < end; ++e)
        acc += g_hw[(size_t)g_csr[e] * NH + c];
    float v = acc + b[c];
    v = v > 0.0f ? v : 0.0f;
    g_y[o] = __float2half_rn(v);
}

// ============================================================================
// xxt = y @ y^T, single fp16 HMMA pass, f32 acc, symmetric triangular grid
#define TILE_BYTES (128 * RS)                 // 34816
#define SMEM_XXT_BYTES (2 * TILE_BYTES)       // 69632 -> occ 2

__device__ __forceinline__ uint32_t smem_u32_of(const void* p) {
    uint32_t a;
    asm("{ .reg .u64 t; cvta.to.shared.u64 t, %1; cvt.u32.u64 %0, t; }"
        : "=r"(a) : "l"(p));
    return a;
}
__device__ __forceinline__ void ldsm_x4(uint32_t r[4], uint32_t addr) {
    asm volatile("ldmatrix.sync.aligned.m8n8.x4.shared.b16 {%0,%1,%2,%3}, [%4];"
                 : "=r"(r[0]), "=r"(r[1]), "=r"(r[2]), "=r"(r[3]) : "r"(addr));
}
__device__ __forceinline__ void cp16(uint32_t dst, const void* src) {
    asm volatile("cp.async.cg.shared.global [%0], [%1], 16;" :: "r"(dst), "l"(src));
}
#define CP_COMMIT() asm volatile("cp.async.commit_group;" ::: "memory")
#define CP_WAIT()   asm volatile("cp.async.wait_all;" ::: "memory")

__device__ __forceinline__ void load_tile_async(const __half* __restrict__ src,
                                                int row0, uint32_t dst) {
    int tid = threadIdx.x;  // 256 threads, 8 x 16B each
    #pragma unroll
    for (int it = 0; it < 8; ++it) {
        int chunk = it * 256 + tid;
        int row = chunk >> 4, c16 = chunk & 15;
        cp16(dst + row * RS + c16 * 16,
             src + (size_t)(row0 + row) * NH + c16 * 8);
    }
}
__device__ __forceinline__ void mma_f32acc(float d[4], const uint32_t a[4],
                                           uint32_t b0, uint32_t b1) {
    asm volatile(
        "mma.sync.aligned.m16n8k16.row.col.f32.f16.f16.f32 "
        "{%0,%1,%2,%3}, {%4,%5,%6,%7}, {%8,%9}, {%0,%1,%2,%3};"
        : "+f"(d[0]), "+f"(d[1]), "+f"(d[2]), "+f"(d[3])
        : "r"(a[0]), "r"(a[1]), "r"(a[2]), "r"(a[3]), "r"(b0), "r"(b1));
}

extern "C" __global__ void __launch_bounds__(256, 2)
xxt_mma_kernel(float* __restrict__ out) {
    // triangular decode: t -> (bym, bxn), bym <= bxn, 79x79 upper triangle
    int t = blockIdx.x;
    int r = (int)((159.0f - sqrtf(25281.0f - 8.0f * (float)t)) * 0.5f);
    if (r < 0) r = 0; if (r > 78) r = 78;
    while ((r + 1) * 79 - ((r + 1) * r) / 2 <= t) ++r;
    while (r * 79 - (r * (r - 1)) / 2 > t) --r;
    int bym = r;
    int bxn = r + (t - (r * 79 - (r * (r - 1)) / 2));
    bool diag = (bxn == bym);

    extern __shared__ char smem[];
    uint32_t uA = smem_u32_of(smem);
    uint32_t uB = uA + TILE_BYTES;

    load_tile_async(g_y, bym * 128, uA);
    if (!diag) load_tile_async(g_y, bxn * 128, uB);
    else       uB = uA;
    CP_COMMIT(); CP_WAIT();
    __syncthreads();

    int tid = threadIdx.x, lane = tid & 31, wid = tid >> 5;
    int wm = wid & 1;
    int wn = wid >> 1;
    int frow = lane >> 2;
    int fcol = 2 * (lane & 3);
    uint32_t laneA = (uint32_t)((lane & 15) * RS + (lane >> 4) * 16);
    uint32_t laneB = (uint32_t)((((lane >> 4) & 1) * 8 + (lane & 7)) * RS
                                + ((lane >> 3) & 1) * 16);

    float acc[4][4][4] = {};

    #pragma unroll
    for (int k0 = 0; k0 < 8; ++k0) {
        uint32_t kb = k0 * 32;
        uint32_t bf[2][4];
        #pragma unroll
        for (int jp = 0; jp < 2; ++jp)
            ldsm_x4(bf[jp], uB + laneB + (uint32_t)((wn * 32 + jp * 16) * RS) + kb);
        #pragma unroll
        for (int i = 0; i < 4; ++i) {
            uint32_t a[4];
            ldsm_x4(a, uA + laneA + (uint32_t)((wm * 64 + i * 16) * RS) + kb);
            #pragma unroll
            for (int jp = 0; jp < 2; ++jp) {
                mma_f32acc(acc[i][2 * jp],     a, bf[jp][0], bf[jp][1]);
                mma_f32acc(acc[i][2 * jp + 1], a, bf[jp][2], bf[jp][3]);
            }
        }
    }

    int m0 = bym * 128, n0 = bxn * 128;
    bool edge = (n0 + 127 >= NN) || (m0 + 127 >= NN);

    // main-tile store C[m][n] (float2)
    #pragma unroll
    for (int i = 0; i < 4; ++i) {
        int rr = wm * 64 + i * 16 + frow;
        #pragma unroll
        for (int j = 0; j < 4; ++j) {
            int c = wn * 32 + j * 8 + fcol;
            if (!edge) {
                *(float2*)&out[(size_t)(m0 + rr) * NN + n0 + c] =
                    make_float2(acc[i][j][0], acc[i][j][1]);
                *(float2*)&out[(size_t)(m0 + rr + 8) * NN + n0 + c] =
                    make_float2(acc[i][j][2], acc[i][j][3]);
            } else {
                int m1 = m0 + rr, m2 = m0 + rr + 8, n = n0 + c;
                if (m1 < NN) {
                    if (n < NN)     out[(size_t)m1 * NN + n]     = acc[i][j][0];
                    if (n + 1 < NN) out[(size_t)m1 * NN + n + 1] = acc[i][j][1];
                }
                if (m2 < NN) {
                    if (n < NN)     out[(size_t)m2 * NN + n]     = acc[i][j][2];
                    if (n + 1 < NN) out[(size_t)m2 * NN + n + 1] = acc[i][j][3];
                }
            }
        }
    }

    // mirror store C[n][m] directly from fragments (off-diagonal only)
    if (!diag) {
        bool nedge = (n0 + 127 >= NN);   // m side always interior (bym <= 77)
        #pragma unroll
        for (int i = 0; i < 4; ++i) {
            int rr = wm * 64 + i * 16 + frow;
            size_t m1 = (size_t)(m0 + rr);
            size_t m2 = (size_t)(m0 + rr + 8);
            #pragma unroll
            for (int j = 0; j < 4; ++j) {
                int c = wn * 32 + j * 8 + fcol;
                size_t n1 = (size_t)(n0 + c), n2 = (size_t)(n0 + c + 1);
                if (!nedge) {
                    out[n1 * NN + m1] = acc[i][j][0];
                    out[n2 * NN + m1] = acc[i][j][1];
                    out[n1 * NN + m2] = acc[i][j][2];
                    out[n2 * NN + m2] = acc[i][j][3];
                } else {
                    if (n1 < NN) { out[n1 * NN + m1] = acc[i][j][0];
                                   out[n1 * NN + m2] = acc[i][j][2]; }
                    if (n2 < NN) { out[n2 * NN + m1] = acc[i][j][1];
                                   out[n2 * NN + m2] = acc[i][j][3]; }
                }
            }
        }
    }
}

// ============================================================================
extern "C" void kernel_launch(void* const* d_in, const int* in_sizes, int n_in,
                              void* d_out, int out_size) {
    const float* h  = (const float*)d_in[0];
    const float* W  = (const float*)d_in[1];
    const float* b  = (const float*)d_in[2];
    const int*   es = (const int*)d_in[3];
    const int*   ed = (const int*)d_in[4];
    float*       out = (float*)d_out;

    const size_t smem_hw = (size_t)2 * 128 * TS_STRIDE * sizeof(float);
    cudaFuncSetAttribute(gemm_hw_kernel,
                         cudaFuncAttributeMaxDynamicSharedMemorySize, (int)smem_hw);
    cudaFuncSetAttribute(xxt_mma_kernel,
                         cudaFuncAttributeMaxDynamicSharedMemorySize, SMEM_XXT_BYTES);

    csr_zero_kernel<<<(NN + 255) / 256, 256>>>();
    csr_count_kernel<<<(NE + 255) / 256, 256>>>(ed);
    csr_scan_kernel<<<1, 1024>>>();
    csr_fill_kernel<<<(NE + 255) / 256, 256>>>(es, ed);

    gemm_hw_kernel<<<(NN + 127) / 128, 256, smem_hw>>>(h, W);
    gather_fuse_kernel<<<NPAD, 128>>>(b);

    xxt_mma_kernel<<<3160, 256, SMEM_XXT_BYTES>>>(out);
}